// round 14
// baseline (speedup 1.0000x reference)
#include <cuda_runtime.h>
#include <cuda_fp16.h>
#include <math.h>

#define B_ 64
#define H_ 4
#define N_ 16384
#define W_ 64
#define D_ 1024
#define P_ 70
#define R_ 280
#define BT 8
#define RT 10
#define ROWS_PB 512   // rows per kdots block
#define NG 8          // pipeline groups (8 batches each)

// Scratch (device globals: allocation-free rule)
__device__ float  g_params[B_ * R_];     // raw GEMM output
__device__ __half g_ebuf[B_ * H_ * N_];  // exp(beta*cos_sim), fp16, 8 MB
__device__ float  g_kv[B_ * H_ * W_];    // key * beta / ||key||
__device__ float  g_hp[B_ * H_ * 8];     // gate, sh0, sh1, sh2, gamma
__device__ float  g_sum[B_ * H_];        // softmax denominators (atomic)

__device__ __forceinline__ float softplusf(float x) {
    return x > 20.f ? x : log1pf(__expf(x));
}

// sm_103a packed f32x2 FMA; operands born as 64-bit pairs -> no packing movs.
__device__ __forceinline__ unsigned long long ff2(unsigned long long a,
                                                  unsigned long long b,
                                                  unsigned long long c) {
    unsigned long long d;
    asm("fma.rn.f32x2 %0, %1, %2, %3;" : "=l"(d) : "l"(a), "l"(b), "l"(c));
    return d;
}
__device__ __forceinline__ float hsum2(unsigned long long v) {
    float x, y;
    asm("mov.b64 {%0, %1}, %2;" : "=f"(x), "=f"(y) : "l"(v));
    return x + y;
}
__device__ __forceinline__ unsigned smem_u32(const void* p) {
    unsigned a;
    asm("{ .reg .u64 t; cvta.to.shared.u64 t, %1; cvt.u32.u64 %0, t; }"
        : "=r"(a) : "l"(p));
    return a;
}
__device__ __forceinline__ void st_cluster_f32(unsigned local_addr,
                                               unsigned rank, float v) {
    asm volatile(
        "{ .reg .b32 ra; mapa.shared::cluster.u32 ra, %0, %1;"
        "  st.shared::cluster.f32 [ra], %2; }"
        :: "r"(local_addr), "r"(rank), "f"(v) : "memory");
}

// ---------------------------------------------------------------------------
// Kernel A: tiled GEMM. Block = (8 batches x 10 rows).
// ---------------------------------------------------------------------------
__global__ __launch_bounds__(256) void kparams(const float* __restrict__ cs,
                                               const float* __restrict__ Wr,
                                               const float* __restrict__ br) {
    extern __shared__ float4 dynp[];
    float4* scs = dynp;
    float4* sw  = dynp + BT * 256;
    int rt = blockIdx.x, bt = blockIdx.y;
    int tid = threadIdx.x;

    const float4* gcs = (const float4*)cs + (size_t)bt * BT * 256;
    #pragma unroll
    for (int i = 0; i < BT; i++) scs[i * 256 + tid] = gcs[i * 256 + tid];
    const float4* gw = (const float4*)Wr + (size_t)rt * RT * 256;
    #pragma unroll
    for (int i = 0; i < RT; i++) sw[i * 256 + tid] = gw[i * 256 + tid];
    __syncthreads();

    int w = tid >> 5, l = tid & 31;
    const float4* a = scs + w * 256;
    #pragma unroll
    for (int rl = 0; rl < RT; rl++) {
        const float4* bv = sw + rl * 256;
        float4 acc = make_float4(0.f, 0.f, 0.f, 0.f);
        #pragma unroll
        for (int j = 0; j < 8; j++) {
            float4 x = a[j * 32 + l], y = bv[j * 32 + l];
            acc.x = fmaf(x.x, y.x, acc.x);
            acc.y = fmaf(x.y, y.y, acc.y);
            acc.z = fmaf(x.z, y.z, acc.z);
            acc.w = fmaf(x.w, y.w, acc.w);
        }
        float s = (acc.x + acc.y) + (acc.z + acc.w);
        #pragma unroll
        for (int o = 16; o; o >>= 1) s += __shfl_xor_sync(0xffffffffu, s, o);
        if (l == 0) {
            int r = rt * RT + rl;
            g_params[(bt * BT + w) * R_ + r] = s + br[r];
        }
    }
}

// ---------------------------------------------------------------------------
// Kernel A2: one warp per (b,h): key norm + activations from raw params.
// ---------------------------------------------------------------------------
__global__ __launch_bounds__(256) void kderive() {
    int gw = (blockIdx.x * 256 + threadIdx.x) >> 5;
    int l = threadIdx.x & 31;
    int b = gw >> 2, h = gw & 3;
    const float* ps = &g_params[b * R_ + h * P_];
    float v0 = ps[l], v1 = ps[l + 32];
    float v2 = (l < 6) ? ps[l + 64] : 0.f;

    float kn2 = fmaf(v0, v0, v1 * v1);
    #pragma unroll
    for (int o = 16; o; o >>= 1) kn2 += __shfl_xor_sync(0xffffffffu, kn2, o);

    float p64 = __shfl_sync(0xffffffffu, v2, 0);
    float p65 = __shfl_sync(0xffffffffu, v2, 1);
    float p66 = __shfl_sync(0xffffffffu, v2, 2);
    float p67 = __shfl_sync(0xffffffffu, v2, 3);
    float p68 = __shfl_sync(0xffffffffu, v2, 4);
    float p69 = __shfl_sync(0xffffffffu, v2, 5);

    float beta = softplusf(p64);
    float scale = beta / fmaxf(sqrtf(kn2), 1e-8f);
    g_kv[gw * W_ + l]      = v0 * scale;
    g_kv[gw * W_ + 32 + l] = v1 * scale;

    if (l == 0) {
        float gate = 1.f / (1.f + __expf(-p65));
        float m = fmaxf(p66, fmaxf(p67, p68));
        float e0 = __expf(p66 - m), e1 = __expf(p67 - m), e2 = __expf(p68 - m);
        float si = 1.f / (e0 + e1 + e2);
        g_hp[gw * 8 + 0] = gate;
        g_hp[gw * 8 + 1] = e0 * si;
        g_hp[gw * 8 + 2] = e1 * si;
        g_hp[gw * 8 + 3] = e2 * si;
        g_hp[gw * 8 + 4] = 1.f + softplusf(p69);
        g_sum[gw] = 0.f;
    }
}

// ---------------------------------------------------------------------------
// Kernel B: stream memory once for a batch group. 4 lanes/row, ulonglong2 ->
// packed FFMA2, 2 CTAs/SM.
// ---------------------------------------------------------------------------
__global__ __launch_bounds__(256, 2) void kdots(const float* __restrict__ mem,
                                                int b0) {
    __shared__ float sraw[ROWS_PB * 5];      // [row][ssq,d0,d1,d2,d3]
    __shared__ __half se[H_ * ROWS_PB];      // staged e values
    __shared__ float sred[32];
    int b = b0 + blockIdx.y;
    int n0 = blockIdx.x * ROWS_PB;
    int tid = threadIdx.x;
    int w = tid >> 5, l = tid & 31;
    int c = l & 3;                           // quarter-segment within row
    int sub = l >> 2;                        // row-within-octet (0..7)

    const ulonglong2* kvp = (const ulonglong2*)(g_kv + b * (H_ * W_));
    ulonglong2 kk[H_][4];
    #pragma unroll
    for (int h = 0; h < H_; h++)
        #pragma unroll
        for (int j = 0; j < 4; j++)
            kk[h][j] = kvp[h * 16 + c + j * 4];

    const ulonglong2* src = (const ulonglong2*)(mem + ((size_t)b * N_ + n0) * W_)
                            + (w * 64 + sub) * 16 + c;

    ulonglong2 mm[4];
    #pragma unroll
    for (int j = 0; j < 4; j++) mm[j] = src[j * 4];

    #pragma unroll 2
    for (int i = 0; i < 8; i++) {
        int r = w * 64 + i * 8 + sub;

        ulonglong2 nx[4];
        if (i < 7) {
            const ulonglong2* np = src + (i + 1) * 8 * 16;
            #pragma unroll
            for (int j = 0; j < 4; j++) nx[j] = np[j * 4];
        }

        unsigned long long ssq = 0, d0 = 0, d1 = 0, d2 = 0, d3 = 0;
        #pragma unroll
        for (int j = 0; j < 4; j++) {
            unsigned long long mx = mm[j].x, my = mm[j].y;
            ssq = ff2(mx, mx, ssq);          ssq = ff2(my, my, ssq);
            d0 = ff2(kk[0][j].x, mx, d0);    d0 = ff2(kk[0][j].y, my, d0);
            d1 = ff2(kk[1][j].x, mx, d1);    d1 = ff2(kk[1][j].y, my, d1);
            d2 = ff2(kk[2][j].x, mx, d2);    d2 = ff2(kk[2][j].y, my, d2);
            d3 = ff2(kk[3][j].x, mx, d3);    d3 = ff2(kk[3][j].y, my, d3);
        }

        float fs = hsum2(ssq);
        float f0 = hsum2(d0), f1 = hsum2(d1), f2 = hsum2(d2), f3 = hsum2(d3);
        #pragma unroll
        for (int o = 2; o; o >>= 1) {
            fs += __shfl_xor_sync(0xffffffffu, fs, o);
            f0 += __shfl_xor_sync(0xffffffffu, f0, o);
            f1 += __shfl_xor_sync(0xffffffffu, f1, o);
            f2 += __shfl_xor_sync(0xffffffffu, f2, o);
            f3 += __shfl_xor_sync(0xffffffffu, f3, o);
        }
        if (c == 0) {
            float* dst = &sraw[r * 5];
            dst[0] = fs; dst[1] = f0; dst[2] = f1; dst[3] = f2; dst[4] = f3;
        }

        #pragma unroll
        for (int j = 0; j < 4; j++) mm[j] = nx[j];
    }
    __syncthreads();

    float s0 = 0.f, s1 = 0.f, s2 = 0.f, s3 = 0.f;
    #pragma unroll
    for (int p = 0; p < 8; p++) {
        int idx = p * 256 + tid;
        int row = idx & (ROWS_PB - 1);
        int h = idx >> 9;
        float ssq = sraw[row * 5];
        float d = sraw[row * 5 + 1 + h];
        float inv = rsqrtf(fmaxf(ssq, 1e-16f));
        __half hv = __float2half(__expf(d * inv));
        se[h * ROWS_PB + row] = hv;
        float e = __half2float(hv);
        if (h == 0) s0 += e; else if (h == 1) s1 += e;
        else if (h == 2) s2 += e; else s3 += e;
    }
    #pragma unroll
    for (int o = 16; o; o >>= 1) {
        s0 += __shfl_xor_sync(0xffffffffu, s0, o);
        s1 += __shfl_xor_sync(0xffffffffu, s1, o);
        s2 += __shfl_xor_sync(0xffffffffu, s2, o);
        s3 += __shfl_xor_sync(0xffffffffu, s3, o);
    }
    if (l == 0) {
        sred[w * 4 + 0] = s0; sred[w * 4 + 1] = s1;
        sred[w * 4 + 2] = s2; sred[w * 4 + 3] = s3;
    }
    __syncthreads();

    const uint2* sep = (const uint2*)se;
    #pragma unroll
    for (int q = 0; q < 2; q++) {
        int j = q * 256 + tid;
        int h = j >> 7, off = j & 127;
        uint2* dst = (uint2*)(g_ebuf + ((size_t)(b * H_ + h)) * N_ + n0);
        dst[off] = sep[j];
    }
    if (tid < 4) {
        float t = 0.f;
        #pragma unroll
        for (int wp = 0; wp < 8; wp++) t += sred[wp * 4 + tid];
        atomicAdd(&g_sum[b * H_ + tid], t);
    }
}

// ---------------------------------------------------------------------------
// Kernel C: cluster of 4 CTAs per (b,h). pw in registers, DSMEM partial-sum
// exchange, single pass. bh0 = group offset.
// ---------------------------------------------------------------------------
__global__ __launch_bounds__(256) __cluster_dims__(4, 1, 1)
void kfinish(const float* __restrict__ prev, float* __restrict__ out, int bh0) {
    __shared__ float s_part[4];
    __shared__ float sred[8];
    int bh = bh0 + (blockIdx.x >> 2);
    unsigned rank = blockIdx.x & 3;
    int tid = threadIdx.x;
    int lane = tid & 31;

    const float* hp = &g_hp[bh * 8];
    float gate = hp[0], sh0 = hp[1], sh1 = hp[2], sh2 = hp[3], gamma = hp[4];
    float a = gate / g_sum[bh];
    float om = 1.f - gate;

    size_t base = (size_t)bh * N_;
    const __half* e = g_ebuf + base;
    const __half2* e2 = (const __half2*)e;
    const float4* p4 = (const float4*)(prev + base);

    float4 pw[4];
    float lsum = 0.f;
    #pragma unroll
    for (int k = 0; k < 4; k++) {
        int i = rank * 1024 + k * 256 + tid;
        float4 p = p4[i];
        float2 ea = __half22float2(e2[2 * i]);
        float2 eb = __half22float2(e2[2 * i + 1]);

        float4 g;
        g.x = fmaf(a, ea.x, om * p.x);
        g.y = fmaf(a, ea.y, om * p.y);
        g.z = fmaf(a, eb.x, om * p.z);
        g.w = fmaf(a, eb.y, om * p.w);

        int n = i * 4;
        float left = __shfl_up_sync(0xffffffffu, g.w, 1);
        float right = __shfl_down_sync(0xffffffffu, g.x, 1);
        if (lane == 0) {
            int nl = (n + N_ - 1) & (N_ - 1);
            left = fmaf(a, __half2float(e[nl]), om * prev[base + nl]);
        }
        if (lane == 31) {
            int nr = (n + 4) & (N_ - 1);
            right = fmaf(a, __half2float(e[nr]), om * prev[base + nr]);
        }

        float v0 = fmaf(sh0, left, fmaf(sh1, g.x, sh2 * g.y));
        float v1 = fmaf(sh0, g.x, fmaf(sh1, g.y, sh2 * g.z));
        float v2 = fmaf(sh0, g.y, fmaf(sh1, g.z, sh2 * g.w));
        float v3 = fmaf(sh0, g.z, fmaf(sh1, g.w, sh2 * right));

        pw[k].x = __powf(v0, gamma);
        pw[k].y = __powf(v1, gamma);
        pw[k].z = __powf(v2, gamma);
        pw[k].w = __powf(v3, gamma);
        lsum += (pw[k].x + pw[k].y) + (pw[k].z + pw[k].w);
    }

    #pragma unroll
    for (int o = 16; o; o >>= 1) lsum += __shfl_xor_sync(0xffffffffu, lsum, o);
    if (lane == 0) sred[tid >> 5] = lsum;
    __syncthreads();
    if (tid == 0) {
        float t = 0.f;
        #pragma unroll
        for (int w = 0; w < 8; w++) t += sred[w];
        unsigned la = smem_u32(&s_part[rank]);
        #pragma unroll
        for (unsigned tr = 0; tr < 4; tr++) st_cluster_f32(la, tr, t);
    }

    asm volatile("barrier.cluster.arrive.aligned;" ::: "memory");
    asm volatile("barrier.cluster.wait.aligned;" ::: "memory");

    float invT = 1.f / (((s_part[0] + s_part[1]) + (s_part[2] + s_part[3]))
                        + 1e-6f);

    float4* o4 = (float4*)(out + base);
    #pragma unroll
    for (int k = 0; k < 4; k++) {
        int i = rank * 1024 + k * 256 + tid;
        float4 v = pw[k];
        v.x *= invT; v.y *= invT; v.z *= invT; v.w *= invT;
        o4[i] = v;
    }
}

// ---------------------------------------------------------------------------
extern "C" void kernel_launch(void* const* d_in, const int* in_sizes, int n_in,
                              void* d_out, int out_size) {
    const float* cs   = (const float*)d_in[0];
    const float* prev = (const float*)d_in[1];
    const float* mem  = (const float*)d_in[2];
    const float* Wr   = (const float*)d_in[3];
    const float* br   = (const float*)d_in[4];
    float* out = (float*)d_out;

    static cudaStream_t s2;
    static cudaEvent_t evA[NG], evB;
    static int inited = 0;
    if (!inited) {
        cudaFuncSetAttribute(kparams, cudaFuncAttributeMaxDynamicSharedMemorySize,
                             (BT + RT) * 256 * 16);
        cudaStreamCreateWithFlags(&s2, cudaStreamNonBlocking);
        for (int g = 0; g < NG; g++)
            cudaEventCreateWithFlags(&evA[g], cudaEventDisableTiming);
        cudaEventCreateWithFlags(&evB, cudaEventDisableTiming);
        inited = 1;
    }

    kparams<<<dim3(R_ / RT, B_ / BT), 256, (BT + RT) * 256 * 16>>>(cs, Wr, br);
    kderive<<<(B_ * H_) / 8, 256>>>();

    const int BG = B_ / NG;                       // batches per group
    for (int g = 0; g < NG; g++) {
        kdots<<<dim3(N_ / ROWS_PB, BG), 256>>>(mem, g * BG);
        cudaEventRecord(evA[g], 0);
        cudaStreamWaitEvent(s2, evA[g], 0);
        kfinish<<<BG * H_ * 4, 256, 0, s2>>>(prev, out, g * BG * H_);
    }
    cudaEventRecord(evB, s2);
    cudaStreamWaitEvent(0, evB, 0);
}

// round 15
// speedup vs baseline: 1.3499x; 1.3499x over previous
#include <cuda_runtime.h>
#include <cuda_fp16.h>
#include <math.h>

#define B_ 64
#define H_ 4
#define N_ 16384
#define W_ 64
#define D_ 1024
#define P_ 70
#define R_ 280
#define BT 8
#define RT 10
#define ROWS_PB 512   // rows per kdots block
#define NG 2          // pipeline groups (32 batches each)

// Scratch (device globals: allocation-free rule)
__device__ float  g_params[B_ * R_];     // raw GEMM output
__device__ __half g_ebuf[B_ * H_ * N_];  // exp(beta*cos_sim), fp16, 8 MB
__device__ float  g_kv[B_ * H_ * W_];    // key * beta / ||key||
__device__ float  g_hp[B_ * H_ * 8];     // gate, sh0, sh1, sh2, gamma
__device__ float  g_sum[B_ * H_];        // softmax denominators (atomic)

__device__ __forceinline__ float softplusf(float x) {
    return x > 20.f ? x : log1pf(__expf(x));
}

// sm_103a packed f32x2 FMA; operands born as 64-bit pairs -> no packing movs.
__device__ __forceinline__ unsigned long long ff2(unsigned long long a,
                                                  unsigned long long b,
                                                  unsigned long long c) {
    unsigned long long d;
    asm("fma.rn.f32x2 %0, %1, %2, %3;" : "=l"(d) : "l"(a), "l"(b), "l"(c));
    return d;
}
__device__ __forceinline__ float hsum2(unsigned long long v) {
    float x, y;
    asm("mov.b64 {%0, %1}, %2;" : "=f"(x), "=f"(y) : "l"(v));
    return x + y;
}
__device__ __forceinline__ unsigned smem_u32(const void* p) {
    unsigned a;
    asm("{ .reg .u64 t; cvta.to.shared.u64 t, %1; cvt.u32.u64 %0, t; }"
        : "=r"(a) : "l"(p));
    return a;
}
__device__ __forceinline__ void st_cluster_f32(unsigned local_addr,
                                               unsigned rank, float v) {
    asm volatile(
        "{ .reg .b32 ra; mapa.shared::cluster.u32 ra, %0, %1;"
        "  st.shared::cluster.f32 [ra], %2; }"
        :: "r"(local_addr), "r"(rank), "f"(v) : "memory");
}

// ---------------------------------------------------------------------------
// Kernel A: tiled GEMM. Block = (8 batches x 10 rows).
// ---------------------------------------------------------------------------
__global__ __launch_bounds__(256) void kparams(const float* __restrict__ cs,
                                               const float* __restrict__ Wr,
                                               const float* __restrict__ br) {
    extern __shared__ float4 dynp[];
    float4* scs = dynp;
    float4* sw  = dynp + BT * 256;
    int rt = blockIdx.x, bt = blockIdx.y;
    int tid = threadIdx.x;

    const float4* gcs = (const float4*)cs + (size_t)bt * BT * 256;
    #pragma unroll
    for (int i = 0; i < BT; i++) scs[i * 256 + tid] = gcs[i * 256 + tid];
    const float4* gw = (const float4*)Wr + (size_t)rt * RT * 256;
    #pragma unroll
    for (int i = 0; i < RT; i++) sw[i * 256 + tid] = gw[i * 256 + tid];
    __syncthreads();

    int w = tid >> 5, l = tid & 31;
    const float4* a = scs + w * 256;
    #pragma unroll
    for (int rl = 0; rl < RT; rl++) {
        const float4* bv = sw + rl * 256;
        float4 acc = make_float4(0.f, 0.f, 0.f, 0.f);
        #pragma unroll
        for (int j = 0; j < 8; j++) {
            float4 x = a[j * 32 + l], y = bv[j * 32 + l];
            acc.x = fmaf(x.x, y.x, acc.x);
            acc.y = fmaf(x.y, y.y, acc.y);
            acc.z = fmaf(x.z, y.z, acc.z);
            acc.w = fmaf(x.w, y.w, acc.w);
        }
        float s = (acc.x + acc.y) + (acc.z + acc.w);
        #pragma unroll
        for (int o = 16; o; o >>= 1) s += __shfl_xor_sync(0xffffffffu, s, o);
        if (l == 0) {
            int r = rt * RT + rl;
            g_params[(bt * BT + w) * R_ + r] = s + br[r];
        }
    }
}

// ---------------------------------------------------------------------------
// Kernel A2: one warp per (b,h): key norm + activations from raw params.
// ---------------------------------------------------------------------------
__global__ __launch_bounds__(256) void kderive() {
    int gw = (blockIdx.x * 256 + threadIdx.x) >> 5;
    int l = threadIdx.x & 31;
    int b = gw >> 2, h = gw & 3;
    const float* ps = &g_params[b * R_ + h * P_];
    float v0 = ps[l], v1 = ps[l + 32];
    float v2 = (l < 6) ? ps[l + 64] : 0.f;

    float kn2 = fmaf(v0, v0, v1 * v1);
    #pragma unroll
    for (int o = 16; o; o >>= 1) kn2 += __shfl_xor_sync(0xffffffffu, kn2, o);

    float p64 = __shfl_sync(0xffffffffu, v2, 0);
    float p65 = __shfl_sync(0xffffffffu, v2, 1);
    float p66 = __shfl_sync(0xffffffffu, v2, 2);
    float p67 = __shfl_sync(0xffffffffu, v2, 3);
    float p68 = __shfl_sync(0xffffffffu, v2, 4);
    float p69 = __shfl_sync(0xffffffffu, v2, 5);

    float beta = softplusf(p64);
    float scale = beta / fmaxf(sqrtf(kn2), 1e-8f);
    g_kv[gw * W_ + l]      = v0 * scale;
    g_kv[gw * W_ + 32 + l] = v1 * scale;

    if (l == 0) {
        float gate = 1.f / (1.f + __expf(-p65));
        float m = fmaxf(p66, fmaxf(p67, p68));
        float e0 = __expf(p66 - m), e1 = __expf(p67 - m), e2 = __expf(p68 - m);
        float si = 1.f / (e0 + e1 + e2);
        g_hp[gw * 8 + 0] = gate;
        g_hp[gw * 8 + 1] = e0 * si;
        g_hp[gw * 8 + 2] = e1 * si;
        g_hp[gw * 8 + 3] = e2 * si;
        g_hp[gw * 8 + 4] = 1.f + softplusf(p69);
        g_sum[gw] = 0.f;
    }
}

// ---------------------------------------------------------------------------
// Kernel B: stream memory once for a batch group. 4 lanes/row, ulonglong2 ->
// packed FFMA2, 2 CTAs/SM.
// ---------------------------------------------------------------------------
__global__ __launch_bounds__(256, 2) void kdots(const float* __restrict__ mem,
                                                int b0) {
    __shared__ float sraw[ROWS_PB * 5];      // [row][ssq,d0,d1,d2,d3]
    __shared__ __half se[H_ * ROWS_PB];      // staged e values
    __shared__ float sred[32];
    int b = b0 + blockIdx.y;
    int n0 = blockIdx.x * ROWS_PB;
    int tid = threadIdx.x;
    int w = tid >> 5, l = tid & 31;
    int c = l & 3;                           // quarter-segment within row
    int sub = l >> 2;                        // row-within-octet (0..7)

    const ulonglong2* kvp = (const ulonglong2*)(g_kv + b * (H_ * W_));
    ulonglong2 kk[H_][4];
    #pragma unroll
    for (int h = 0; h < H_; h++)
        #pragma unroll
        for (int j = 0; j < 4; j++)
            kk[h][j] = kvp[h * 16 + c + j * 4];

    const ulonglong2* src = (const ulonglong2*)(mem + ((size_t)b * N_ + n0) * W_)
                            + (w * 64 + sub) * 16 + c;

    ulonglong2 mm[4];
    #pragma unroll
    for (int j = 0; j < 4; j++) mm[j] = src[j * 4];

    #pragma unroll 2
    for (int i = 0; i < 8; i++) {
        int r = w * 64 + i * 8 + sub;

        ulonglong2 nx[4];
        if (i < 7) {
            const ulonglong2* np = src + (i + 1) * 8 * 16;
            #pragma unroll
            for (int j = 0; j < 4; j++) nx[j] = np[j * 4];
        }

        unsigned long long ssq = 0, d0 = 0, d1 = 0, d2 = 0, d3 = 0;
        #pragma unroll
        for (int j = 0; j < 4; j++) {
            unsigned long long mx = mm[j].x, my = mm[j].y;
            ssq = ff2(mx, mx, ssq);          ssq = ff2(my, my, ssq);
            d0 = ff2(kk[0][j].x, mx, d0);    d0 = ff2(kk[0][j].y, my, d0);
            d1 = ff2(kk[1][j].x, mx, d1);    d1 = ff2(kk[1][j].y, my, d1);
            d2 = ff2(kk[2][j].x, mx, d2);    d2 = ff2(kk[2][j].y, my, d2);
            d3 = ff2(kk[3][j].x, mx, d3);    d3 = ff2(kk[3][j].y, my, d3);
        }

        float fs = hsum2(ssq);
        float f0 = hsum2(d0), f1 = hsum2(d1), f2 = hsum2(d2), f3 = hsum2(d3);
        #pragma unroll
        for (int o = 2; o; o >>= 1) {
            fs += __shfl_xor_sync(0xffffffffu, fs, o);
            f0 += __shfl_xor_sync(0xffffffffu, f0, o);
            f1 += __shfl_xor_sync(0xffffffffu, f1, o);
            f2 += __shfl_xor_sync(0xffffffffu, f2, o);
            f3 += __shfl_xor_sync(0xffffffffu, f3, o);
        }
        if (c == 0) {
            float* dst = &sraw[r * 5];
            dst[0] = fs; dst[1] = f0; dst[2] = f1; dst[3] = f2; dst[4] = f3;
        }

        #pragma unroll
        for (int j = 0; j < 4; j++) mm[j] = nx[j];
    }
    __syncthreads();

    float s0 = 0.f, s1 = 0.f, s2 = 0.f, s3 = 0.f;
    #pragma unroll
    for (int p = 0; p < 8; p++) {
        int idx = p * 256 + tid;
        int row = idx & (ROWS_PB - 1);
        int h = idx >> 9;
        float ssq = sraw[row * 5];
        float d = sraw[row * 5 + 1 + h];
        float inv = rsqrtf(fmaxf(ssq, 1e-16f));
        __half hv = __float2half(__expf(d * inv));
        se[h * ROWS_PB + row] = hv;
        float e = __half2float(hv);
        if (h == 0) s0 += e; else if (h == 1) s1 += e;
        else if (h == 2) s2 += e; else s3 += e;
    }
    #pragma unroll
    for (int o = 16; o; o >>= 1) {
        s0 += __shfl_xor_sync(0xffffffffu, s0, o);
        s1 += __shfl_xor_sync(0xffffffffu, s1, o);
        s2 += __shfl_xor_sync(0xffffffffu, s2, o);
        s3 += __shfl_xor_sync(0xffffffffu, s3, o);
    }
    if (l == 0) {
        sred[w * 4 + 0] = s0; sred[w * 4 + 1] = s1;
        sred[w * 4 + 2] = s2; sred[w * 4 + 3] = s3;
    }
    __syncthreads();

    const uint2* sep = (const uint2*)se;
    #pragma unroll
    for (int q = 0; q < 2; q++) {
        int j = q * 256 + tid;
        int h = j >> 7, off = j & 127;
        uint2* dst = (uint2*)(g_ebuf + ((size_t)(b * H_ + h)) * N_ + n0);
        dst[off] = sep[j];
    }
    if (tid < 4) {
        float t = 0.f;
        #pragma unroll
        for (int wp = 0; wp < 8; wp++) t += sred[wp * 4 + tid];
        atomicAdd(&g_sum[b * H_ + tid], t);
    }
}

// ---------------------------------------------------------------------------
// Kernel C: cluster of 4 CTAs per (b,h). pw in registers, DSMEM partial-sum
// exchange, single pass. bh0 = group offset.
// ---------------------------------------------------------------------------
__global__ __launch_bounds__(256) __cluster_dims__(4, 1, 1)
void kfinish(const float* __restrict__ prev, float* __restrict__ out, int bh0) {
    __shared__ float s_part[4];
    __shared__ float sred[8];
    int bh = bh0 + (blockIdx.x >> 2);
    unsigned rank = blockIdx.x & 3;
    int tid = threadIdx.x;
    int lane = tid & 31;

    const float* hp = &g_hp[bh * 8];
    float gate = hp[0], sh0 = hp[1], sh1 = hp[2], sh2 = hp[3], gamma = hp[4];
    float a = gate / g_sum[bh];
    float om = 1.f - gate;

    size_t base = (size_t)bh * N_;
    const __half* e = g_ebuf + base;
    const __half2* e2 = (const __half2*)e;
    const float4* p4 = (const float4*)(prev + base);

    float4 pw[4];
    float lsum = 0.f;
    #pragma unroll
    for (int k = 0; k < 4; k++) {
        int i = rank * 1024 + k * 256 + tid;
        float4 p = p4[i];
        float2 ea = __half22float2(e2[2 * i]);
        float2 eb = __half22float2(e2[2 * i + 1]);

        float4 g;
        g.x = fmaf(a, ea.x, om * p.x);
        g.y = fmaf(a, ea.y, om * p.y);
        g.z = fmaf(a, eb.x, om * p.z);
        g.w = fmaf(a, eb.y, om * p.w);

        int n = i * 4;
        float left = __shfl_up_sync(0xffffffffu, g.w, 1);
        float right = __shfl_down_sync(0xffffffffu, g.x, 1);
        if (lane == 0) {
            int nl = (n + N_ - 1) & (N_ - 1);
            left = fmaf(a, __half2float(e[nl]), om * prev[base + nl]);
        }
        if (lane == 31) {
            int nr = (n + 4) & (N_ - 1);
            right = fmaf(a, __half2float(e[nr]), om * prev[base + nr]);
        }

        float v0 = fmaf(sh0, left, fmaf(sh1, g.x, sh2 * g.y));
        float v1 = fmaf(sh0, g.x, fmaf(sh1, g.y, sh2 * g.z));
        float v2 = fmaf(sh0, g.y, fmaf(sh1, g.z, sh2 * g.w));
        float v3 = fmaf(sh0, g.z, fmaf(sh1, g.w, sh2 * right));

        pw[k].x = __powf(v0, gamma);
        pw[k].y = __powf(v1, gamma);
        pw[k].z = __powf(v2, gamma);
        pw[k].w = __powf(v3, gamma);
        lsum += (pw[k].x + pw[k].y) + (pw[k].z + pw[k].w);
    }

    #pragma unroll
    for (int o = 16; o; o >>= 1) lsum += __shfl_xor_sync(0xffffffffu, lsum, o);
    if (lane == 0) sred[tid >> 5] = lsum;
    __syncthreads();
    if (tid == 0) {
        float t = 0.f;
        #pragma unroll
        for (int w = 0; w < 8; w++) t += sred[w];
        unsigned la = smem_u32(&s_part[rank]);
        #pragma unroll
        for (unsigned tr = 0; tr < 4; tr++) st_cluster_f32(la, tr, t);
    }

    asm volatile("barrier.cluster.arrive.aligned;" ::: "memory");
    asm volatile("barrier.cluster.wait.aligned;" ::: "memory");

    float invT = 1.f / (((s_part[0] + s_part[1]) + (s_part[2] + s_part[3]))
                        + 1e-6f);

    float4* o4 = (float4*)(out + base);
    #pragma unroll
    for (int k = 0; k < 4; k++) {
        int i = rank * 1024 + k * 256 + tid;
        float4 v = pw[k];
        v.x *= invT; v.y *= invT; v.z *= invT; v.w *= invT;
        o4[i] = v;
    }
}

// ---------------------------------------------------------------------------
extern "C" void kernel_launch(void* const* d_in, const int* in_sizes, int n_in,
                              void* d_out, int out_size) {
    const float* cs   = (const float*)d_in[0];
    const float* prev = (const float*)d_in[1];
    const float* mem  = (const float*)d_in[2];
    const float* Wr   = (const float*)d_in[3];
    const float* br   = (const float*)d_in[4];
    float* out = (float*)d_out;

    static cudaStream_t s2;
    static cudaEvent_t evA[NG], evB;
    static int inited = 0;
    if (!inited) {
        cudaFuncSetAttribute(kparams, cudaFuncAttributeMaxDynamicSharedMemorySize,
                             (BT + RT) * 256 * 16);
        cudaStreamCreateWithFlags(&s2, cudaStreamNonBlocking);
        for (int g = 0; g < NG; g++)
            cudaEventCreateWithFlags(&evA[g], cudaEventDisableTiming);
        cudaEventCreateWithFlags(&evB, cudaEventDisableTiming);
        inited = 1;
    }

    kparams<<<dim3(R_ / RT, B_ / BT), 256, (BT + RT) * 256 * 16>>>(cs, Wr, br);
    kderive<<<(B_ * H_) / 8, 256>>>();

    const int BG = B_ / NG;                       // 32 batches per group
    // stream 0: both kdots groups back-to-back (keeps DRAM saturated)
    for (int g = 0; g < NG; g++) {
        kdots<<<dim3(N_ / ROWS_PB, BG), 256>>>(mem, g * BG);
        cudaEventRecord(evA[g], 0);
    }
    // stream 2: kfinish(g) after kdots(g); g0 overlaps kdots(g1)
    for (int g = 0; g < NG; g++) {
        cudaStreamWaitEvent(s2, evA[g], 0);
        kfinish<<<BG * H_ * 4, 256, 0, s2>>>(prev, out, g * BG * H_);
    }
    cudaEventRecord(evB, s2);
    cudaStreamWaitEvent(0, evB, 0);
}

// round 16
// speedup vs baseline: 1.4199x; 1.0519x over previous
#include <cuda_runtime.h>
#include <cuda_fp16.h>
#include <math.h>

#define B_ 64
#define H_ 4
#define N_ 16384
#define W_ 64
#define D_ 1024
#define P_ 70
#define R_ 280
#define BT 8
#define RT 10
#define ROWS_PB 512   // rows per kdots block

// Scratch (device globals: allocation-free rule)
__device__ float  g_params[B_ * R_];     // raw GEMM output
__device__ __half g_ebuf[B_ * H_ * N_];  // exp(beta*cos_sim), fp16, 8 MB
__device__ float  g_kv[B_ * H_ * W_];    // key * beta / ||key||
__device__ float  g_hp[B_ * H_ * 8];     // gate, sh0, sh1, sh2, gamma
__device__ float  g_sum[B_ * H_];        // softmax denominators (atomic)

__device__ __forceinline__ float softplusf(float x) {
    return x > 20.f ? x : log1pf(__expf(x));
}

// sm_103a packed f32x2 FMA; operands born as 64-bit pairs -> no packing movs.
__device__ __forceinline__ unsigned long long ff2(unsigned long long a,
                                                  unsigned long long b,
                                                  unsigned long long c) {
    unsigned long long d;
    asm("fma.rn.f32x2 %0, %1, %2, %3;" : "=l"(d) : "l"(a), "l"(b), "l"(c));
    return d;
}
__device__ __forceinline__ float hsum2(unsigned long long v) {
    float x, y;
    asm("mov.b64 {%0, %1}, %2;" : "=f"(x), "=f"(y) : "l"(v));
    return x + y;
}
__device__ __forceinline__ unsigned smem_u32(const void* p) {
    unsigned a;
    asm("{ .reg .u64 t; cvta.to.shared.u64 t, %1; cvt.u32.u64 %0, t; }"
        : "=r"(a) : "l"(p));
    return a;
}
__device__ __forceinline__ void st_cluster_f32(unsigned local_addr,
                                               unsigned rank, float v) {
    asm volatile(
        "{ .reg .b32 ra; mapa.shared::cluster.u32 ra, %0, %1;"
        "  st.shared::cluster.f32 [ra], %2; }"
        :: "r"(local_addr), "r"(rank), "f"(v) : "memory");
}

// ---------------------------------------------------------------------------
// Kernel A: tiled GEMM. Block = (8 batches x 10 rows).
// ---------------------------------------------------------------------------
__global__ __launch_bounds__(256) void kparams(const float* __restrict__ cs,
                                               const float* __restrict__ Wr,
                                               const float* __restrict__ br) {
    extern __shared__ float4 dynp[];
    float4* scs = dynp;
    float4* sw  = dynp + BT * 256;
    int rt = blockIdx.x, bt = blockIdx.y;
    int tid = threadIdx.x;

    const float4* gcs = (const float4*)cs + (size_t)bt * BT * 256;
    #pragma unroll
    for (int i = 0; i < BT; i++) scs[i * 256 + tid] = gcs[i * 256 + tid];
    const float4* gw = (const float4*)Wr + (size_t)rt * RT * 256;
    #pragma unroll
    for (int i = 0; i < RT; i++) sw[i * 256 + tid] = gw[i * 256 + tid];
    __syncthreads();

    int w = tid >> 5, l = tid & 31;
    const float4* a = scs + w * 256;
    #pragma unroll
    for (int rl = 0; rl < RT; rl++) {
        const float4* bv = sw + rl * 256;
        float4 acc = make_float4(0.f, 0.f, 0.f, 0.f);
        #pragma unroll
        for (int j = 0; j < 8; j++) {
            float4 x = a[j * 32 + l], y = bv[j * 32 + l];
            acc.x = fmaf(x.x, y.x, acc.x);
            acc.y = fmaf(x.y, y.y, acc.y);
            acc.z = fmaf(x.z, y.z, acc.z);
            acc.w = fmaf(x.w, y.w, acc.w);
        }
        float s = (acc.x + acc.y) + (acc.z + acc.w);
        #pragma unroll
        for (int o = 16; o; o >>= 1) s += __shfl_xor_sync(0xffffffffu, s, o);
        if (l == 0) {
            int r = rt * RT + rl;
            g_params[(bt * BT + w) * R_ + r] = s + br[r];
        }
    }
}

// ---------------------------------------------------------------------------
// Kernel A2: one warp per (b,h): key norm + activations from raw params.
// ---------------------------------------------------------------------------
__global__ __launch_bounds__(256) void kderive() {
    int gw = (blockIdx.x * 256 + threadIdx.x) >> 5;
    int l = threadIdx.x & 31;
    int b = gw >> 2, h = gw & 3;
    const float* ps = &g_params[b * R_ + h * P_];
    float v0 = ps[l], v1 = ps[l + 32];
    float v2 = (l < 6) ? ps[l + 64] : 0.f;

    float kn2 = fmaf(v0, v0, v1 * v1);
    #pragma unroll
    for (int o = 16; o; o >>= 1) kn2 += __shfl_xor_sync(0xffffffffu, kn2, o);

    float p64 = __shfl_sync(0xffffffffu, v2, 0);
    float p65 = __shfl_sync(0xffffffffu, v2, 1);
    float p66 = __shfl_sync(0xffffffffu, v2, 2);
    float p67 = __shfl_sync(0xffffffffu, v2, 3);
    float p68 = __shfl_sync(0xffffffffu, v2, 4);
    float p69 = __shfl_sync(0xffffffffu, v2, 5);

    float beta = softplusf(p64);
    float scale = beta / fmaxf(sqrtf(kn2), 1e-8f);
    g_kv[gw * W_ + l]      = v0 * scale;
    g_kv[gw * W_ + 32 + l] = v1 * scale;

    if (l == 0) {
        float gate = 1.f / (1.f + __expf(-p65));
        float m = fmaxf(p66, fmaxf(p67, p68));
        float e0 = __expf(p66 - m), e1 = __expf(p67 - m), e2 = __expf(p68 - m);
        float si = 1.f / (e0 + e1 + e2);
        g_hp[gw * 8 + 0] = gate;
        g_hp[gw * 8 + 1] = e0 * si;
        g_hp[gw * 8 + 2] = e1 * si;
        g_hp[gw * 8 + 3] = e2 * si;
        g_hp[gw * 8 + 4] = 1.f + softplusf(p69);
        g_sum[gw] = 0.f;
    }
}

// ---------------------------------------------------------------------------
// Kernel B: stream memory once. 8 lanes/row (low reg pressure: keys = 32
// regs), ulonglong2 -> packed FFMA2, 3 CTAs/SM for latency hiding.
// ---------------------------------------------------------------------------
__global__ __launch_bounds__(256, 3) void kdots(const float* __restrict__ mem) {
    __shared__ float sraw[ROWS_PB * 5];      // [row][ssq,d0,d1,d2,d3]
    __shared__ __half se[H_ * ROWS_PB];      // staged e values
    __shared__ float sred[32];
    int b = blockIdx.y;
    int n0 = blockIdx.x * ROWS_PB;
    int tid = threadIdx.x;
    int w = tid >> 5, l = tid & 31;
    int c = l & 7;                           // 16B-chunk index within row half
    int sub = l >> 3;                        // row-within-quad (0..3)

    // keys: head h = 16 ulonglong2; this lane takes chunks c and c+8
    const ulonglong2* kvp = (const ulonglong2*)(g_kv + b * (H_ * W_));
    ulonglong2 kka[H_], kkb[H_];
    #pragma unroll
    for (int h = 0; h < H_; h++) {
        kka[h] = kvp[h * 16 + c];
        kkb[h] = kvp[h * 16 + c + 8];
    }

    const ulonglong2* src = (const ulonglong2*)(mem + ((size_t)b * N_ + n0) * W_);

    #pragma unroll 4
    for (int i = 0; i < 16; i++) {
        int r = w * 64 + i * 4 + sub;
        const ulonglong2* rp = src + r * 16;
        ulonglong2 m0 = rp[c];
        ulonglong2 m1 = rp[c + 8];

        unsigned long long ssq = 0, d0 = 0, d1 = 0, d2 = 0, d3 = 0;
        ssq = ff2(m0.x, m0.x, ssq);      ssq = ff2(m0.y, m0.y, ssq);
        ssq = ff2(m1.x, m1.x, ssq);      ssq = ff2(m1.y, m1.y, ssq);
        d0 = ff2(kka[0].x, m0.x, d0);    d0 = ff2(kka[0].y, m0.y, d0);
        d0 = ff2(kkb[0].x, m1.x, d0);    d0 = ff2(kkb[0].y, m1.y, d0);
        d1 = ff2(kka[1].x, m0.x, d1);    d1 = ff2(kka[1].y, m0.y, d1);
        d1 = ff2(kkb[1].x, m1.x, d1);    d1 = ff2(kkb[1].y, m1.y, d1);
        d2 = ff2(kka[2].x, m0.x, d2);    d2 = ff2(kka[2].y, m0.y, d2);
        d2 = ff2(kkb[2].x, m1.x, d2);    d2 = ff2(kkb[2].y, m1.y, d2);
        d3 = ff2(kka[3].x, m0.x, d3);    d3 = ff2(kka[3].y, m0.y, d3);
        d3 = ff2(kkb[3].x, m1.x, d3);    d3 = ff2(kkb[3].y, m1.y, d3);

        float fs = hsum2(ssq);
        float f0 = hsum2(d0), f1 = hsum2(d1), f2 = hsum2(d2), f3 = hsum2(d3);
        #pragma unroll
        for (int o = 4; o; o >>= 1) {
            fs += __shfl_xor_sync(0xffffffffu, fs, o);
            f0 += __shfl_xor_sync(0xffffffffu, f0, o);
            f1 += __shfl_xor_sync(0xffffffffu, f1, o);
            f2 += __shfl_xor_sync(0xffffffffu, f2, o);
            f3 += __shfl_xor_sync(0xffffffffu, f3, o);
        }
        if (c == 0) {
            float* dst = &sraw[r * 5];
            dst[0] = fs; dst[1] = f0; dst[2] = f1; dst[3] = f2; dst[4] = f3;
        }
    }
    __syncthreads();

    // packed epilogue: 2048 (h,row) exps over 256 threads; stride-5 LDS
    // conflict-free (gcd(5,32)=1)
    float s0 = 0.f, s1 = 0.f, s2 = 0.f, s3 = 0.f;
    #pragma unroll
    for (int p = 0; p < 8; p++) {
        int idx = p * 256 + tid;
        int row = idx & (ROWS_PB - 1);
        int h = idx >> 9;
        float ssq = sraw[row * 5];
        float d = sraw[row * 5 + 1 + h];
        float inv = rsqrtf(fmaxf(ssq, 1e-16f));
        __half hv = __float2half(__expf(d * inv));
        se[h * ROWS_PB + row] = hv;
        float e = __half2float(hv);
        if (h == 0) s0 += e; else if (h == 1) s1 += e;
        else if (h == 2) s2 += e; else s3 += e;
    }
    #pragma unroll
    for (int o = 16; o; o >>= 1) {
        s0 += __shfl_xor_sync(0xffffffffu, s0, o);
        s1 += __shfl_xor_sync(0xffffffffu, s1, o);
        s2 += __shfl_xor_sync(0xffffffffu, s2, o);
        s3 += __shfl_xor_sync(0xffffffffu, s3, o);
    }
    if (l == 0) {
        sred[w * 4 + 0] = s0; sred[w * 4 + 1] = s1;
        sred[w * 4 + 2] = s2; sred[w * 4 + 3] = s3;
    }
    __syncthreads();

    const uint2* sep = (const uint2*)se;
    #pragma unroll
    for (int q = 0; q < 2; q++) {
        int j = q * 256 + tid;
        int h = j >> 7, off = j & 127;
        uint2* dst = (uint2*)(g_ebuf + ((size_t)(b * H_ + h)) * N_ + n0);
        dst[off] = sep[j];
    }
    if (tid < 4) {
        float t = 0.f;
        #pragma unroll
        for (int wp = 0; wp < 8; wp++) t += sred[wp * 4 + tid];
        atomicAdd(&g_sum[b * H_ + tid], t);
    }
}

// ---------------------------------------------------------------------------
// Kernel C: cluster of 4 CTAs per (b,h). pw in registers, DSMEM partial-sum
// exchange, single pass.
// ---------------------------------------------------------------------------
__global__ __launch_bounds__(256) __cluster_dims__(4, 1, 1)
void kfinish(const float* __restrict__ prev, float* __restrict__ out) {
    __shared__ float s_part[4];
    __shared__ float sred[8];
    int bh = blockIdx.x >> 2;
    unsigned rank = blockIdx.x & 3;
    int tid = threadIdx.x;
    int lane = tid & 31;

    const float* hp = &g_hp[bh * 8];
    float gate = hp[0], sh0 = hp[1], sh1 = hp[2], sh2 = hp[3], gamma = hp[4];
    float a = gate / g_sum[bh];
    float om = 1.f - gate;

    size_t base = (size_t)bh * N_;
    const __half* e = g_ebuf + base;
    const __half2* e2 = (const __half2*)e;
    const float4* p4 = (const float4*)(prev + base);

    float4 pw[4];
    float lsum = 0.f;
    #pragma unroll
    for (int k = 0; k < 4; k++) {
        int i = rank * 1024 + k * 256 + tid;
        float4 p = p4[i];
        float2 ea = __half22float2(e2[2 * i]);
        float2 eb = __half22float2(e2[2 * i + 1]);

        float4 g;
        g.x = fmaf(a, ea.x, om * p.x);
        g.y = fmaf(a, ea.y, om * p.y);
        g.z = fmaf(a, eb.x, om * p.z);
        g.w = fmaf(a, eb.y, om * p.w);

        int n = i * 4;
        float left = __shfl_up_sync(0xffffffffu, g.w, 1);
        float right = __shfl_down_sync(0xffffffffu, g.x, 1);
        if (lane == 0) {
            int nl = (n + N_ - 1) & (N_ - 1);
            left = fmaf(a, __half2float(e[nl]), om * prev[base + nl]);
        }
        if (lane == 31) {
            int nr = (n + 4) & (N_ - 1);
            right = fmaf(a, __half2float(e[nr]), om * prev[base + nr]);
        }

        float v0 = fmaf(sh0, left, fmaf(sh1, g.x, sh2 * g.y));
        float v1 = fmaf(sh0, g.x, fmaf(sh1, g.y, sh2 * g.z));
        float v2 = fmaf(sh0, g.y, fmaf(sh1, g.z, sh2 * g.w));
        float v3 = fmaf(sh0, g.z, fmaf(sh1, g.w, sh2 * right));

        pw[k].x = __powf(v0, gamma);
        pw[k].y = __powf(v1, gamma);
        pw[k].z = __powf(v2, gamma);
        pw[k].w = __powf(v3, gamma);
        lsum += (pw[k].x + pw[k].y) + (pw[k].z + pw[k].w);
    }

    #pragma unroll
    for (int o = 16; o; o >>= 1) lsum += __shfl_xor_sync(0xffffffffu, lsum, o);
    if (lane == 0) sred[tid >> 5] = lsum;
    __syncthreads();
    if (tid == 0) {
        float t = 0.f;
        #pragma unroll
        for (int w = 0; w < 8; w++) t += sred[w];
        unsigned la = smem_u32(&s_part[rank]);
        #pragma unroll
        for (unsigned tr = 0; tr < 4; tr++) st_cluster_f32(la, tr, t);
    }

    asm volatile("barrier.cluster.arrive.aligned;" ::: "memory");
    asm volatile("barrier.cluster.wait.aligned;" ::: "memory");

    float invT = 1.f / (((s_part[0] + s_part[1]) + (s_part[2] + s_part[3]))
                        + 1e-6f);

    float4* o4 = (float4*)(out + base);
    #pragma unroll
    for (int k = 0; k < 4; k++) {
        int i = rank * 1024 + k * 256 + tid;
        float4 v = pw[k];
        v.x *= invT; v.y *= invT; v.z *= invT; v.w *= invT;
        o4[i] = v;
    }
}

// ---------------------------------------------------------------------------
extern "C" void kernel_launch(void* const* d_in, const int* in_sizes, int n_in,
                              void* d_out, int out_size) {
    const float* cs   = (const float*)d_in[0];
    const float* prev = (const float*)d_in[1];
    const float* mem  = (const float*)d_in[2];
    const float* Wr   = (const float*)d_in[3];
    const float* br   = (const float*)d_in[4];
    float* out = (float*)d_out;

    static int inited = 0;
    if (!inited) {
        cudaFuncSetAttribute(kparams, cudaFuncAttributeMaxDynamicSharedMemorySize,
                             (BT + RT) * 256 * 16);
        inited = 1;
    }

    kparams<<<dim3(R_ / RT, B_ / BT), 256, (BT + RT) * 256 * 16>>>(cs, Wr, br);
    kderive<<<(B_ * H_) / 8, 256>>>();
    kdots<<<dim3(N_ / ROWS_PB, B_), 256>>>(mem);
    kfinish<<<B_ * H_ * 4, 256>>>(prev, out);
}

// round 17
// speedup vs baseline: 1.5843x; 1.1158x over previous
#include <cuda_runtime.h>
#include <cuda_fp16.h>
#include <math.h>

#define B_ 64
#define H_ 4
#define N_ 16384
#define W_ 64
#define D_ 1024
#define P_ 70
#define R_ 280
#define BT 8
#define RT 10
#define STG_ROWS 128                  // rows per cp.async stage
#define STAGES 4                      // 512 rows per block
#define ROWF4 17                      // padded row stride in float4
#define BUF_F4 (STG_ROWS * ROWF4)     // float4 per stage buffer
#define DYN_SMEM ((2 * BUF_F4 + 64) * 16)   // 2 buffers + 64 ulonglong2 keys

// Scratch (device globals: allocation-free rule)
__device__ float  g_params[B_ * R_];     // raw GEMM output
__device__ __half g_ebuf[B_ * H_ * N_];  // exp(beta*cos_sim), fp16, 8 MB
__device__ float  g_kv[B_ * H_ * W_];    // key * beta / ||key||
__device__ float  g_hp[B_ * H_ * 8];     // gate, sh0, sh1, sh2, gamma
__device__ float  g_sum[B_ * H_];        // softmax denominators (atomic)

__device__ __forceinline__ float softplusf(float x) {
    return x > 20.f ? x : log1pf(__expf(x));
}

// sm_103a packed f32x2 FMA; operands born as 64-bit pairs -> no packing movs.
__device__ __forceinline__ unsigned long long ff2(unsigned long long a,
                                                  unsigned long long b,
                                                  unsigned long long c) {
    unsigned long long d;
    asm("fma.rn.f32x2 %0, %1, %2, %3;" : "=l"(d) : "l"(a), "l"(b), "l"(c));
    return d;
}
__device__ __forceinline__ float hsum2(unsigned long long v) {
    float x, y;
    asm("mov.b64 {%0, %1}, %2;" : "=f"(x), "=f"(y) : "l"(v));
    return x + y;
}
__device__ __forceinline__ unsigned smem_u32(const void* p) {
    unsigned a;
    asm("{ .reg .u64 t; cvta.to.shared.u64 t, %1; cvt.u32.u64 %0, t; }"
        : "=r"(a) : "l"(p));
    return a;
}
__device__ __forceinline__ void st_cluster_f32(unsigned local_addr,
                                               unsigned rank, float v) {
    asm volatile(
        "{ .reg .b32 ra; mapa.shared::cluster.u32 ra, %0, %1;"
        "  st.shared::cluster.f32 [ra], %2; }"
        :: "r"(local_addr), "r"(rank), "f"(v) : "memory");
}
__device__ __forceinline__ void cp16(unsigned saddr, const void* gaddr) {
    asm volatile("cp.async.cg.shared.global [%0], [%1], 16;"
                 :: "r"(saddr), "l"(gaddr));
}

// ---------------------------------------------------------------------------
// Kernel A: tiled GEMM. Block = (8 batches x 10 rows).
// ---------------------------------------------------------------------------
__global__ __launch_bounds__(256) void kparams(const float* __restrict__ cs,
                                               const float* __restrict__ Wr,
                                               const float* __restrict__ br) {
    extern __shared__ float4 dynp[];
    float4* scs = dynp;
    float4* sw  = dynp + BT * 256;
    int rt = blockIdx.x, bt = blockIdx.y;
    int tid = threadIdx.x;

    const float4* gcs = (const float4*)cs + (size_t)bt * BT * 256;
    #pragma unroll
    for (int i = 0; i < BT; i++) scs[i * 256 + tid] = gcs[i * 256 + tid];
    const float4* gw = (const float4*)Wr + (size_t)rt * RT * 256;
    #pragma unroll
    for (int i = 0; i < RT; i++) sw[i * 256 + tid] = gw[i * 256 + tid];
    __syncthreads();

    int w = tid >> 5, l = tid & 31;
    const float4* a = scs + w * 256;
    #pragma unroll
    for (int rl = 0; rl < RT; rl++) {
        const float4* bv = sw + rl * 256;
        float4 acc = make_float4(0.f, 0.f, 0.f, 0.f);
        #pragma unroll
        for (int j = 0; j < 8; j++) {
            float4 x = a[j * 32 + l], y = bv[j * 32 + l];
            acc.x = fmaf(x.x, y.x, acc.x);
            acc.y = fmaf(x.y, y.y, acc.y);
            acc.z = fmaf(x.z, y.z, acc.z);
            acc.w = fmaf(x.w, y.w, acc.w);
        }
        float s = (acc.x + acc.y) + (acc.z + acc.w);
        #pragma unroll
        for (int o = 16; o; o >>= 1) s += __shfl_xor_sync(0xffffffffu, s, o);
        if (l == 0) {
            int r = rt * RT + rl;
            g_params[(bt * BT + w) * R_ + r] = s + br[r];
        }
    }
}

// ---------------------------------------------------------------------------
// Kernel A2: one warp per (b,h): key norm + activations from raw params.
// ---------------------------------------------------------------------------
__global__ __launch_bounds__(256) void kderive() {
    int gw = (blockIdx.x * 256 + threadIdx.x) >> 5;
    int l = threadIdx.x & 31;
    int b = gw >> 2, h = gw & 3;
    const float* ps = &g_params[b * R_ + h * P_];
    float v0 = ps[l], v1 = ps[l + 32];
    float v2 = (l < 6) ? ps[l + 64] : 0.f;

    float kn2 = fmaf(v0, v0, v1 * v1);
    #pragma unroll
    for (int o = 16; o; o >>= 1) kn2 += __shfl_xor_sync(0xffffffffu, kn2, o);

    float p64 = __shfl_sync(0xffffffffu, v2, 0);
    float p65 = __shfl_sync(0xffffffffu, v2, 1);
    float p66 = __shfl_sync(0xffffffffu, v2, 2);
    float p67 = __shfl_sync(0xffffffffu, v2, 3);
    float p68 = __shfl_sync(0xffffffffu, v2, 4);
    float p69 = __shfl_sync(0xffffffffu, v2, 5);

    float beta = softplusf(p64);
    float scale = beta / fmaxf(sqrtf(kn2), 1e-8f);
    g_kv[gw * W_ + l]      = v0 * scale;
    g_kv[gw * W_ + 32 + l] = v1 * scale;

    if (l == 0) {
        float gate = 1.f / (1.f + __expf(-p65));
        float m = fmaxf(p66, fmaxf(p67, p68));
        float e0 = __expf(p66 - m), e1 = __expf(p67 - m), e2 = __expf(p68 - m);
        float si = 1.f / (e0 + e1 + e2);
        g_hp[gw * 8 + 0] = gate;
        g_hp[gw * 8 + 1] = e0 * si;
        g_hp[gw * 8 + 2] = e1 * si;
        g_hp[gw * 8 + 3] = e2 * si;
        g_hp[gw * 8 + 4] = 1.f + softplusf(p69);
        g_sum[gw] = 0.f;
    }
}

// ---------------------------------------------------------------------------
// Kernel B: cp.async double-buffered stream. All 256 threads feed the async
// queue (in-flight bytes live in smem, not registers); threads 0..127 each
// compute ONE full row from padded smem (zero shuffles, keys broadcast).
// ---------------------------------------------------------------------------
__global__ __launch_bounds__(256) void kdots(const float* __restrict__ mem) {
    extern __shared__ float4 dyn[];          // [2][BUF_F4] bufs | 64 ull2 keys
    __shared__ float sred[16];
    int b = blockIdx.y;
    int n0 = blockIdx.x * (STG_ROWS * STAGES);
    int tid = threadIdx.x;
    int w = tid >> 5, l = tid & 31;

    ulonglong2* skv = (ulonglong2*)(dyn + 2 * BUF_F4);
    if (tid < 64) skv[tid] = ((const ulonglong2*)(g_kv + b * (H_ * W_)))[tid];

    const char* gbase = (const char*)(mem + ((size_t)b * N_ + n0) * W_);
    unsigned sb[2] = { smem_u32(dyn), smem_u32(dyn + BUF_F4) };

    // prologue: issue stages 0 and 1
    #pragma unroll
    for (int st = 0; st < 2; st++) {
        const char* gsrc = gbase + (size_t)st * STG_ROWS * 256;
        #pragma unroll
        for (int k = 0; k < 8; k++) {
            int g = tid + k * 256;
            unsigned sa = sb[st] + ((g >> 4) * ROWF4 + (g & 15)) * 16;
            cp16(sa, gsrc + g * 16);
        }
        asm volatile("cp.async.commit_group;");
    }

    float a0 = 0.f, a1 = 0.f, a2 = 0.f, a3 = 0.f;   // fp16-rounded e sums

    #pragma unroll
    for (int s = 0; s < STAGES; s++) {
        if (s < STAGES - 1)
            asm volatile("cp.async.wait_group 1;" ::: "memory");
        else
            asm volatile("cp.async.wait_group 0;" ::: "memory");
        __syncthreads();

        if (tid < STG_ROWS) {
            const ulonglong2* mr =
                (const ulonglong2*)(dyn + (s & 1) * BUF_F4 + tid * ROWF4);
            unsigned long long ssq = 0, d0 = 0, d1 = 0, d2 = 0, d3 = 0;
            #pragma unroll
            for (int j = 0; j < 16; j++) {
                ulonglong2 m = mr[j];
                ssq = ff2(m.x, m.x, ssq);         ssq = ff2(m.y, m.y, ssq);
                ulonglong2 k0 = skv[j];
                d0 = ff2(k0.x, m.x, d0);          d0 = ff2(k0.y, m.y, d0);
                ulonglong2 k1 = skv[16 + j];
                d1 = ff2(k1.x, m.x, d1);          d1 = ff2(k1.y, m.y, d1);
                ulonglong2 k2 = skv[32 + j];
                d2 = ff2(k2.x, m.x, d2);          d2 = ff2(k2.y, m.y, d2);
                ulonglong2 k3 = skv[48 + j];
                d3 = ff2(k3.x, m.x, d3);          d3 = ff2(k3.y, m.y, d3);
            }
            float inv = rsqrtf(fmaxf(hsum2(ssq), 1e-16f));
            __half h0 = __float2half(__expf(hsum2(d0) * inv));
            __half h1 = __float2half(__expf(hsum2(d1) * inv));
            __half h2 = __float2half(__expf(hsum2(d2) * inv));
            __half h3 = __float2half(__expf(hsum2(d3) * inv));
            size_t eo = (size_t)(b * H_) * N_ + n0 + s * STG_ROWS + tid;
            g_ebuf[eo]           = h0;
            g_ebuf[eo + N_]      = h1;
            g_ebuf[eo + 2 * N_]  = h2;
            g_ebuf[eo + 3 * N_]  = h3;
            a0 += __half2float(h0);
            a1 += __half2float(h1);
            a2 += __half2float(h2);
            a3 += __half2float(h3);
        }
        __syncthreads();

        if (s < STAGES - 2) {
            int st = s + 2;
            const char* gsrc = gbase + (size_t)st * STG_ROWS * 256;
            #pragma unroll
            for (int k = 0; k < 8; k++) {
                int g = tid + k * 256;
                unsigned sa = sb[st & 1] + ((g >> 4) * ROWF4 + (g & 15)) * 16;
                cp16(sa, gsrc + g * 16);
            }
            asm volatile("cp.async.commit_group;");
        }
    }

    // reduce partial sums: warps 0..3 hold all contributions
    if (tid < STG_ROWS) {
        #pragma unroll
        for (int o = 16; o; o >>= 1) {
            a0 += __shfl_xor_sync(0xffffffffu, a0, o);
            a1 += __shfl_xor_sync(0xffffffffu, a1, o);
            a2 += __shfl_xor_sync(0xffffffffu, a2, o);
            a3 += __shfl_xor_sync(0xffffffffu, a3, o);
        }
        if (l == 0) {
            sred[w * 4 + 0] = a0; sred[w * 4 + 1] = a1;
            sred[w * 4 + 2] = a2; sred[w * 4 + 3] = a3;
        }
    }
    __syncthreads();
    if (tid < 4) {
        float t = sred[tid] + sred[4 + tid] + sred[8 + tid] + sred[12 + tid];
        atomicAdd(&g_sum[b * H_ + tid], t);
    }
}

// ---------------------------------------------------------------------------
// Kernel C: cluster of 4 CTAs per (b,h). pw in registers, DSMEM partial-sum
// exchange, single pass.
// ---------------------------------------------------------------------------
__global__ __launch_bounds__(256) __cluster_dims__(4, 1, 1)
void kfinish(const float* __restrict__ prev, float* __restrict__ out) {
    __shared__ float s_part[4];
    __shared__ float sred[8];
    int bh = blockIdx.x >> 2;
    unsigned rank = blockIdx.x & 3;
    int tid = threadIdx.x;
    int lane = tid & 31;

    const float* hp = &g_hp[bh * 8];
    float gate = hp[0], sh0 = hp[1], sh1 = hp[2], sh2 = hp[3], gamma = hp[4];
    float a = gate / g_sum[bh];
    float om = 1.f - gate;

    size_t base = (size_t)bh * N_;
    const __half* e = g_ebuf + base;
    const __half2* e2 = (const __half2*)e;
    const float4* p4 = (const float4*)(prev + base);

    float4 pw[4];
    float lsum = 0.f;
    #pragma unroll
    for (int k = 0; k < 4; k++) {
        int i = rank * 1024 + k * 256 + tid;
        float4 p = p4[i];
        float2 ea = __half22float2(e2[2 * i]);
        float2 eb = __half22float2(e2[2 * i + 1]);

        float4 g;
        g.x = fmaf(a, ea.x, om * p.x);
        g.y = fmaf(a, ea.y, om * p.y);
        g.z = fmaf(a, eb.x, om * p.z);
        g.w = fmaf(a, eb.y, om * p.w);

        int n = i * 4;
        float left = __shfl_up_sync(0xffffffffu, g.w, 1);
        float right = __shfl_down_sync(0xffffffffu, g.x, 1);
        if (lane == 0) {
            int nl = (n + N_ - 1) & (N_ - 1);
            left = fmaf(a, __half2float(e[nl]), om * prev[base + nl]);
        }
        if (lane == 31) {
            int nr = (n + 4) & (N_ - 1);
            right = fmaf(a, __half2float(e[nr]), om * prev[base + nr]);
        }

        float v0 = fmaf(sh0, left, fmaf(sh1, g.x, sh2 * g.y));
        float v1 = fmaf(sh0, g.x, fmaf(sh1, g.y, sh2 * g.z));
        float v2 = fmaf(sh0, g.y, fmaf(sh1, g.z, sh2 * g.w));
        float v3 = fmaf(sh0, g.z, fmaf(sh1, g.w, sh2 * right));

        pw[k].x = __powf(v0, gamma);
        pw[k].y = __powf(v1, gamma);
        pw[k].z = __powf(v2, gamma);
        pw[k].w = __powf(v3, gamma);
        lsum += (pw[k].x + pw[k].y) + (pw[k].z + pw[k].w);
    }

    #pragma unroll
    for (int o = 16; o; o >>= 1) lsum += __shfl_xor_sync(0xffffffffu, lsum, o);
    if (lane == 0) sred[tid >> 5] = lsum;
    __syncthreads();
    if (tid == 0) {
        float t = 0.f;
        #pragma unroll
        for (int w = 0; w < 8; w++) t += sred[w];
        unsigned la = smem_u32(&s_part[rank]);
        #pragma unroll
        for (unsigned tr = 0; tr < 4; tr++) st_cluster_f32(la, tr, t);
    }

    asm volatile("barrier.cluster.arrive.aligned;" ::: "memory");
    asm volatile("barrier.cluster.wait.aligned;" ::: "memory");

    float invT = 1.f / (((s_part[0] + s_part[1]) + (s_part[2] + s_part[3]))
                        + 1e-6f);

    float4* o4 = (float4*)(out + base);
    #pragma unroll
    for (int k = 0; k < 4; k++) {
        int i = rank * 1024 + k * 256 + tid;
        float4 v = pw[k];
        v.x *= invT; v.y *= invT; v.z *= invT; v.w *= invT;
        o4[i] = v;
    }
}

// ---------------------------------------------------------------------------
extern "C" void kernel_launch(void* const* d_in, const int* in_sizes, int n_in,
                              void* d_out, int out_size) {
    const float* cs   = (const float*)d_in[0];
    const float* prev = (const float*)d_in[1];
    const float* mem  = (const float*)d_in[2];
    const float* Wr   = (const float*)d_in[3];
    const float* br   = (const float*)d_in[4];
    float* out = (float*)d_out;

    static int inited = 0;
    if (!inited) {
        cudaFuncSetAttribute(kparams, cudaFuncAttributeMaxDynamicSharedMemorySize,
                             (BT + RT) * 256 * 16);
        cudaFuncSetAttribute(kdots, cudaFuncAttributeMaxDynamicSharedMemorySize,
                             DYN_SMEM);
        inited = 1;
    }

    kparams<<<dim3(R_ / RT, B_ / BT), 256, (BT + RT) * 256 * 16>>>(cs, Wr, br);
    kderive<<<(B_ * H_) / 8, 256>>>();
    kdots<<<dim3(N_ / (STG_ROWS * STAGES), B_), 256, DYN_SMEM>>>(mem);
    kfinish<<<B_ * H_ * 4, 256>>>(prev, out);
}